// round 16
// baseline (speedup 1.0000x reference)
#include <cuda_runtime.h>
#include <cuda_fp16.h>
#include <cstdint>

#define BATCH  4
#define SEQ    4096
#define DIM    64
#define BM     64
#define BN     64
#define NSPLIT 4
#define NQB    (SEQ / BM)                 // 64
#define NP     (NQB * BATCH * NSPLIT)     // 1024
#define ROWB    144                       // bytes per padded smem row
#define STAGE_BYTES (2 * 64 * ROWB)       // K + V tiles = 18432 B
#define NSTAGE 3
#define SMEM_BYTES  (NSTAGE * STAGE_BYTES + NSTAGE * BN * 4)   // 56064 B

#define LOG2E   1.44269504088896340736f
#define SCL2    (0.125f * LOG2E)          // 1/sqrt(64) * log2(e)
#define NEGL2   (10000.0f * LOG2E)        // additive penalty, log2 domain

#define CONVROWS 128                      // rows per conv block (1-wave grid)
#define NCONV    (BATCH * (SEQ / CONVROWS))   // 128

__device__ float  g_l[NP * BM];
__device__ float  g_o[(size_t)NP * BM * DIM];
__device__ int    g_first[BATCH];
__device__ __half g_Kh[(size_t)BATCH * SEQ * DIM];   // [b][s][d] fp16
__device__ __half g_Vt[(size_t)BATCH * DIM * SEQ];   // [b][d][s] fp16 (transposed)

__device__ __forceinline__ float ex2(float x) {
    float y;
    asm("ex2.approx.ftz.f32 %0, %1;" : "=f"(y) : "f"(x));
    return y;
}

__device__ __forceinline__ void mma_f16(float* d, const uint32_t* a, uint32_t b0, uint32_t b1) {
    asm volatile("mma.sync.aligned.m16n8k16.row.col.f32.f16.f16.f32 "
        "{%0,%1,%2,%3},{%4,%5,%6,%7},{%8,%9},{%0,%1,%2,%3};"
        : "+f"(d[0]), "+f"(d[1]), "+f"(d[2]), "+f"(d[3])
        : "r"(a[0]), "r"(a[1]), "r"(a[2]), "r"(a[3]), "r"(b0), "r"(b1));
}

__device__ __forceinline__ void ldsm_x4(uint32_t& r0, uint32_t& r1, uint32_t& r2, uint32_t& r3,
                                        uint32_t addr) {
    asm volatile("ldmatrix.sync.aligned.m8n8.x4.shared.b16 {%0,%1,%2,%3}, [%4];"
        : "=r"(r0), "=r"(r1), "=r"(r2), "=r"(r3) : "r"(addr));
}

__device__ __forceinline__ uint32_t h2u(__half2 h) { return *reinterpret_cast<uint32_t*>(&h); }

// ---- prologue: K->fp16 [b][s][d]; V->fp16 transposed [b][d][s]; + mask scan.
//      128-row tiles x 512 threads: 132 blocks = one wave, MLP 8/thread. ----
__global__ __launch_bounds__(512)
void conv_kernel(const float* __restrict__ K, const float* __restrict__ V,
                 const int* __restrict__ mask) {
    __shared__ __half Vs[CONVROWS][72];
    __shared__ int best;
    const int blk = blockIdx.x;
    const int tid = threadIdx.x;

    if (blk >= NCONV) {                              // mask-scan blocks
        const int b = blk - NCONV;
        if (tid == 0) best = SEQ;
        __syncthreads();
        int loc = SEQ;
        const int4* mp = reinterpret_cast<const int4*>(mask + b * SEQ);
        #pragma unroll
        for (int i = 1; i >= 0; i--) {               // descending: final loc = smallest hit
            int4 v = mp[tid + i * 512];
            int base = (tid + i * 512) * 4;
            if (v.w) loc = base + 3;
            if (v.z) loc = base + 2;
            if (v.y) loc = base + 1;
            if (v.x) loc = base;
        }
        atomicMin(&best, loc);
        __syncthreads();
        if (tid == 0) g_first[b] = best;
        return;
    }

    const int b  = blk >> 5;                         // 32 tiles per batch
    const int kb = (blk & 31) * CONVROWS;
    const int ky = tid >> 2, dseg = (tid & 3) * 16;  // row 0..127, 16-dim segment

    const float4* kp = reinterpret_cast<const float4*>(K + ((size_t)(b * SEQ + kb + ky)) * DIM + dseg);
    const float4* vp = reinterpret_cast<const float4*>(V + ((size_t)(b * SEQ + kb + ky)) * DIM + dseg);
    uint2* kout = reinterpret_cast<uint2*>(g_Kh + ((size_t)(b * SEQ + kb + ky)) * DIM + dseg);
    #pragma unroll
    for (int i = 0; i < 4; i++) {
        float4 f = kp[i];
        kout[i] = make_uint2(h2u(__floats2half2_rn(f.x, f.y)), h2u(__floats2half2_rn(f.z, f.w)));
        float4 v = vp[i];
        Vs[ky][dseg + i * 4 + 0] = __float2half(v.x);
        Vs[ky][dseg + i * 4 + 1] = __float2half(v.y);
        Vs[ky][dseg + i * 4 + 2] = __float2half(v.z);
        Vs[ky][dseg + i * 4 + 3] = __float2half(v.w);
    }
    __syncthreads();
    const int d = tid >> 3, kseg = (tid & 7) * 16;   // d 0..63, 16-s segment
    uint4* vout = reinterpret_cast<uint4*>(g_Vt + ((size_t)(b * DIM + d)) * SEQ + kb + kseg);
    #pragma unroll
    for (int i = 0; i < 2; i++) {
        __half2 h0 = __halves2half2(Vs[kseg + i * 8 + 0][d], Vs[kseg + i * 8 + 1][d]);
        __half2 h1 = __halves2half2(Vs[kseg + i * 8 + 2][d], Vs[kseg + i * 8 + 3][d]);
        __half2 h2 = __halves2half2(Vs[kseg + i * 8 + 4][d], Vs[kseg + i * 8 + 5][d]);
        __half2 h3 = __halves2half2(Vs[kseg + i * 8 + 6][d], Vs[kseg + i * 8 + 7][d]);
        vout[i] = make_uint4(h2u(h0), h2u(h1), h2u(h2), h2u(h3));
    }
}

__global__ __launch_bounds__(128)
void sdpa_split_kernel(const float* __restrict__ Q, const int* __restrict__ mask) {
    extern __shared__ char smraw[];
    float* pen_base = reinterpret_cast<float*>(smraw + NSTAGE * STAGE_BYTES);
    const uint32_t smem_u = (uint32_t)__cvta_generic_to_shared(smraw);

    const int tid  = threadIdx.x;
    const int lane = tid & 31;
    const int warp = tid >> 5;
    const int g    = lane >> 2;
    const int tig  = lane & 3;
    const int row8 = lane & 7, matid = lane >> 3;

    const int bx = blockIdx.x;
    const int s  = bx & 3;
    const int b  = (bx >> 2) & 3;
    const int qb = (NQB - 1) - (bx >> 4);             // longest q-blocks first
    const int qm = qb * BM;
    const int p  = bx;
    const int* mb = mask + b * SEQ;
    const int first_b = g_first[b];

    // Fixed-base softmax (no online max); per-row base shift
    // rowadj_r = (r >= first_b) ? 0 : NEGL2 (R11 derivation).
    // Causal term per tile (uniform in t): t<qb none; t==qb per-element;
    // t>qb uniform -NEGL2 (degenerate full-span blocks only).
    const int n_tiles = (first_b <= qm) ? (qb + 1) : (SEQ / BN);

    const int chunk = (n_tiles + NSPLIT - 1) / NSPLIT;
    const int t_beg = s * chunk;
    const int t_end = min(t_beg + chunk, n_tiles);

    const int lr0 = warp * 16 + g;
    const int lr1 = lr0 + 8;

    if (t_beg >= t_end) {                             // empty split: sentinel
        if (tig == 0) {
            g_l[p * BM + lr0] = 0.0f;
            g_l[p * BM + lr1] = 0.0f;
        }
        return;
    }

    const int r0 = qm + lr0;
    const int r1 = qm + lr1;
    const float adj0 = (r0 >= first_b) ? 0.0f : NEGL2;
    const float adj1 = (r1 >= first_b) ? 0.0f : NEGL2;

    // Q fragments (fp16, m16n8k16 A layout), 4 k-chunks x 4 regs
    uint32_t qf[4][4];
    {
        const float* q0 = Q + ((size_t)b * SEQ + r0) * DIM;
        const float* q1 = Q + ((size_t)b * SEQ + r1) * DIM;
        #pragma unroll
        for (int kc = 0; kc < 4; kc++) {
            float2 x0 = *reinterpret_cast<const float2*>(q0 + kc * 16 + 2 * tig);
            float2 x1 = *reinterpret_cast<const float2*>(q1 + kc * 16 + 2 * tig);
            float2 y0 = *reinterpret_cast<const float2*>(q0 + kc * 16 + 8 + 2 * tig);
            float2 y1 = *reinterpret_cast<const float2*>(q1 + kc * 16 + 8 + 2 * tig);
            qf[kc][0] = h2u(__floats2half2_rn(x0.x, x0.y));
            qf[kc][1] = h2u(__floats2half2_rn(x1.x, x1.y));
            qf[kc][2] = h2u(__floats2half2_rn(y0.x, y0.y));
            qf[kc][3] = h2u(__floats2half2_rn(y1.x, y1.y));
        }
    }

    float o[8][4];
    #pragma unroll
    for (int i = 0; i < 8; i++)
        o[i][0] = o[i][1] = o[i][2] = o[i][3] = 0.0f;
    float l0 = 0.0f, l1 = 0.0f;

    const char* kgbase = reinterpret_cast<const char*>(g_Kh + ((size_t)b * SEQ) * DIM);
    const char* vgbase = reinterpret_cast<const char*>(g_Vt + ((size_t)b * DIM) * SEQ);

    auto issue = [&](int t, int st) {
        const int kv0 = t * BN;
        const char* ksrc = kgbase + (size_t)kv0 * DIM * 2;
        const char* vsrc = vgbase + (size_t)kv0 * 2;
        char* kdst = smraw + st * STAGE_BYTES;
        char* vdst = kdst + 64 * ROWB;
        #pragma unroll
        for (int i = 0; i < 4; i++) {
            const int c = tid + i * 128;              // 0..511
            const int row = c >> 3, seg = c & 7;
            uint32_t ka = (uint32_t)__cvta_generic_to_shared(kdst + row * ROWB + seg * 16);
            asm volatile("cp.async.cg.shared.global [%0], [%1], 16;"
                :: "r"(ka), "l"(ksrc + (row * DIM + seg * 8) * 2));
            uint32_t va = (uint32_t)__cvta_generic_to_shared(vdst + row * ROWB + seg * 16);
            asm volatile("cp.async.cg.shared.global [%0], [%1], 16;"
                :: "r"(va), "l"(vsrc + (size_t)row * SEQ * 2 + seg * 16));
        }
        float* penf = pen_base + st * BN;
        if (tid < BN) penf[tid] = mb[kv0 + tid] ? 0.0f : -NEGL2;
        asm volatile("cp.async.commit_group;");
    };

    // 3-stage ring, ONE sync per tile. issue(t+2) happens AFTER the sync at
    // iter t, which proves all warps finished iter t-1 — the last reader of
    // stage (t+2)%3 — so the overwrite is race-free.
    issue(t_beg, 0);
    if (t_beg + 1 < t_end) issue(t_beg + 1, 1);

    for (int t = t_beg; t < t_end; t++) {
        const int st  = (t - t_beg) % NSTAGE;
        const int kv0 = t * BN;

        if (t + 1 < t_end) {
            asm volatile("cp.async.wait_group 1;");   // tile t complete (t+1 may pend)
        } else {
            asm volatile("cp.async.wait_group 0;");
        }
        __syncthreads();
        if (t + 2 < t_end) issue(t + 2, (t + 2 - t_beg) % NSTAGE);

        const uint32_t kbase_u = smem_u + st * STAGE_BYTES;
        const uint32_t vbase_u = kbase_u + 64 * ROWB;
        const float* penf = pen_base + st * BN;

        // ---- S = Q K^T : B fragments via ldmatrix.x4 on K tile ----
        float sc[8][4];
        #pragma unroll
        for (int nc = 0; nc < 8; nc++)
            sc[nc][0] = sc[nc][1] = sc[nc][2] = sc[nc][3] = 0.0f;
        #pragma unroll
        for (int kc = 0; kc < 4; kc++) {
            #pragma unroll
            for (int np = 0; np < 4; np++) {
                uint32_t addr = kbase_u + ((2 * np + (matid >> 1)) * 8 + row8) * ROWB
                              + (kc * 16 + (matid & 1) * 8) * 2;
                uint32_t r0_, r1_, r2_, r3_;
                ldsm_x4(r0_, r1_, r2_, r3_, addr);
                mma_f16(sc[2 * np],     qf[kc], r0_, r1_);
                mma_f16(sc[2 * np + 1], qf[kc], r2_, r3_);
            }
        }

        // ---- P = exp2(...) ; causal term specialized on uniform t ----
        if (t == qb) {                                 // diagonal tile
            #pragma unroll
            for (int nc = 0; nc < 8; nc++) {
                const int c0 = kv0 + nc * 8 + 2 * tig;
                float2 pn = *reinterpret_cast<const float2*>(penf + nc * 8 + 2 * tig);
                sc[nc][0] = ex2(sc[nc][0] * SCL2 + pn.x + adj0 + (c0     > r0 ? -NEGL2 : 0.0f));
                sc[nc][1] = ex2(sc[nc][1] * SCL2 + pn.y + adj0 + (c0 + 1 > r0 ? -NEGL2 : 0.0f));
                sc[nc][2] = ex2(sc[nc][2] * SCL2 + pn.x + adj1 + (c0     > r1 ? -NEGL2 : 0.0f));
                sc[nc][3] = ex2(sc[nc][3] * SCL2 + pn.y + adj1 + (c0 + 1 > r1 ? -NEGL2 : 0.0f));
                l0 += sc[nc][0] + sc[nc][1];
                l1 += sc[nc][2] + sc[nc][3];
            }
        } else {
            const float cc = (t > qb) ? -NEGL2 : 0.0f; // uniform causal term
            const float a0 = adj0 + cc, a1 = adj1 + cc;
            #pragma unroll
            for (int nc = 0; nc < 8; nc++) {
                float2 pn = *reinterpret_cast<const float2*>(penf + nc * 8 + 2 * tig);
                sc[nc][0] = ex2(sc[nc][0] * SCL2 + pn.x + a0);
                sc[nc][1] = ex2(sc[nc][1] * SCL2 + pn.y + a0);
                sc[nc][2] = ex2(sc[nc][2] * SCL2 + pn.x + a1);
                sc[nc][3] = ex2(sc[nc][3] * SCL2 + pn.y + a1);
                l0 += sc[nc][0] + sc[nc][1];
                l1 += sc[nc][2] + sc[nc][3];
            }
        }

        // ---- O += P V : A = packed S frags (layout chains, no shuffles);
        //      B via ldmatrix.x4 on transposed V tile ----
        #pragma unroll
        for (int kk = 0; kk < 4; kk++) {
            uint32_t pf[4];
            pf[0] = h2u(__floats2half2_rn(sc[2 * kk][0],     sc[2 * kk][1]));
            pf[1] = h2u(__floats2half2_rn(sc[2 * kk][2],     sc[2 * kk][3]));
            pf[2] = h2u(__floats2half2_rn(sc[2 * kk + 1][0], sc[2 * kk + 1][1]));
            pf[3] = h2u(__floats2half2_rn(sc[2 * kk + 1][2], sc[2 * kk + 1][3]));
            #pragma unroll
            for (int op = 0; op < 4; op++) {
                uint32_t addr = vbase_u + ((2 * op + (matid >> 1)) * 8 + row8) * ROWB
                              + (kk * 16 + (matid & 1) * 8) * 2;
                uint32_t r0_, r1_, r2_, r3_;
                ldsm_x4(r0_, r1_, r2_, r3_, addr);
                mma_f16(o[2 * op],     pf, r0_, r1_);
                mma_f16(o[2 * op + 1], pf, r2_, r3_);
            }
        }
    }

    // quad-reduce l (full row sum)
    l0 += __shfl_xor_sync(0xffffffffu, l0, 1);
    l0 += __shfl_xor_sync(0xffffffffu, l0, 2);
    l1 += __shfl_xor_sync(0xffffffffu, l1, 1);
    l1 += __shfl_xor_sync(0xffffffffu, l1, 2);

    float* po0 = g_o + ((size_t)p * BM + lr0) * DIM;
    float* po1 = g_o + ((size_t)p * BM + lr1) * DIM;
    #pragma unroll
    for (int oc = 0; oc < 8; oc++) {
        const int c = oc * 8 + 2 * tig;
        *reinterpret_cast<float2*>(po0 + c) = make_float2(o[oc][0], o[oc][1]);
        *reinterpret_cast<float2*>(po1 + c) = make_float2(o[oc][2], o[oc][3]);
    }
    if (tig == 0) {
        g_l[p * BM + lr0] = l0;
        g_l[p * BM + lr1] = l1;
    }
}

__global__ __launch_bounds__(256)
void combine_kernel(float* __restrict__ O) {
    const int t  = blockIdx.x * 256 + threadIdx.x;
    const int fq  = t & 15;
    const int row = (t >> 4) & 63;
    const int qb  = (t >> 10) & 63;
    const int b   = t >> 16;

    const int qidx  = (NQB - 1) - qb;
    const int pbase = (qidx << 4) | (b << 2);

    // all splits share the same fixed exp2 base per row -> plain sums
    float L = 0.0f;
    float4 acc = make_float4(0.f, 0.f, 0.f, 0.f);
    #pragma unroll
    for (int s2 = 0; s2 < NSPLIT; s2++) {
        float lv = g_l[(pbase + s2) * BM + row];
        L += lv;
        if (lv > 0.0f) {
            float4 v = reinterpret_cast<const float4*>(
                g_o + ((size_t)(pbase + s2) * BM + row) * DIM)[fq];
            acc.x += v.x; acc.y += v.y; acc.z += v.z; acc.w += v.w;
        }
    }
    const float inv = 1.0f / L;
    reinterpret_cast<float4*>(O + ((size_t)b * SEQ + qb * BM + row) * DIM)[fq] =
        make_float4(acc.x * inv, acc.y * inv, acc.z * inv, acc.w * inv);
}

extern "C" void kernel_launch(void* const* d_in, const int* in_sizes, int n_in,
                              void* d_out, int out_size) {
    const float* Q    = (const float*)d_in[0];
    const float* K    = (const float*)d_in[1];
    const float* V    = (const float*)d_in[2];
    const int*   mask = (const int*)d_in[3];
    float*       O    = (float*)d_out;

    static bool attr_set = false;
    if (!attr_set) {
        cudaFuncSetAttribute(sdpa_split_kernel,
                             cudaFuncAttributeMaxDynamicSharedMemorySize, SMEM_BYTES);
        attr_set = true;
    }

    conv_kernel<<<NCONV + BATCH, 512>>>(K, V, mask);
    sdpa_split_kernel<<<NP, 128, SMEM_BYTES>>>(Q, mask);
    combine_kernel<<<(BATCH * SEQ * DIM / 4) / 256, 256>>>(O);
}

// round 17
// speedup vs baseline: 1.0675x; 1.0675x over previous
#include <cuda_runtime.h>
#include <cuda_fp16.h>
#include <cstdint>

#define BATCH  4
#define SEQ    4096
#define DIM    64
#define BM     64
#define BN     64
#define NSPLIT 4
#define NQB    (SEQ / BM)                 // 64
#define NP     (NQB * BATCH * NSPLIT)     // 1024
#define ROWB    144                       // bytes per padded smem row
#define STAGE_BYTES (2 * 64 * ROWB)       // K + V tiles = 18432 B
#define SMEM_BYTES  (2 * STAGE_BYTES + 2 * BN * 4)   // 37376 B

#define LOG2E   1.44269504088896340736f
#define SCL2    (0.125f * LOG2E)          // 1/sqrt(64) * log2(e)
#define NEGL2   (10000.0f * LOG2E)        // additive penalty, log2 domain

#define NCONV   512                       // streaming-convert blocks (K:256, V:256)

__device__ float  g_l[NP * BM];
__device__ float  g_o[(size_t)NP * BM * DIM];
__device__ int    g_first[BATCH];
__device__ __half g_Kh[(size_t)BATCH * SEQ * DIM];   // [b][s][d] fp16
__device__ __half g_Vh[(size_t)BATCH * SEQ * DIM];   // [b][s][d] fp16 (row-major!)

__device__ __forceinline__ float ex2(float x) {
    float y;
    asm("ex2.approx.ftz.f32 %0, %1;" : "=f"(y) : "f"(x));
    return y;
}

__device__ __forceinline__ void mma_f16(float* d, const uint32_t* a, uint32_t b0, uint32_t b1) {
    asm volatile("mma.sync.aligned.m16n8k16.row.col.f32.f16.f16.f32 "
        "{%0,%1,%2,%3},{%4,%5,%6,%7},{%8,%9},{%0,%1,%2,%3};"
        : "+f"(d[0]), "+f"(d[1]), "+f"(d[2]), "+f"(d[3])
        : "r"(a[0]), "r"(a[1]), "r"(a[2]), "r"(a[3]), "r"(b0), "r"(b1));
}

__device__ __forceinline__ void ldsm_x4(uint32_t& r0, uint32_t& r1, uint32_t& r2, uint32_t& r3,
                                        uint32_t addr) {
    asm volatile("ldmatrix.sync.aligned.m8n8.x4.shared.b16 {%0,%1,%2,%3}, [%4];"
        : "=r"(r0), "=r"(r1), "=r"(r2), "=r"(r3) : "r"(addr));
}

__device__ __forceinline__ void ldsm_x4t(uint32_t& r0, uint32_t& r1, uint32_t& r2, uint32_t& r3,
                                         uint32_t addr) {
    asm volatile("ldmatrix.sync.aligned.m8n8.x4.trans.shared.b16 {%0,%1,%2,%3}, [%4];"
        : "=r"(r0), "=r"(r1), "=r"(r2), "=r"(r3) : "r"(addr));
}

__device__ __forceinline__ uint32_t h2u(__half2 h) { return *reinterpret_cast<uint32_t*>(&h); }

// ---- prologue: pure streaming K,V -> fp16 [b][s][d] (no smem, no transpose);
//      + mask scan blocks ----
__global__ __launch_bounds__(256)
void conv_kernel(const float* __restrict__ K, const float* __restrict__ V,
                 const int* __restrict__ mask) {
    __shared__ int best;
    const int blk = blockIdx.x;
    const int tid = threadIdx.x;

    if (blk >= NCONV) {                              // mask-scan blocks
        const int b = blk - NCONV;
        if (tid == 0) best = SEQ;
        __syncthreads();
        int loc = SEQ;
        const int4* mp = reinterpret_cast<const int4*>(mask + b * SEQ);
        #pragma unroll
        for (int i = 3; i >= 0; i--) {               // descending: final loc = smallest hit
            int4 v = mp[tid + i * 256];
            int base = (tid + i * 256) * 4;
            if (v.w) loc = base + 3;
            if (v.z) loc = base + 2;
            if (v.y) loc = base + 1;
            if (v.x) loc = base;
        }
        atomicMin(&best, loc);
        __syncthreads();
        if (tid == 0) g_first[b] = best;
        return;
    }

    const bool  isv = blk >= 256;
    const float4* src = reinterpret_cast<const float4*>(isv ? V : K)
                      + (size_t)(blk & 255) * 1024;
    uint2* dst = reinterpret_cast<uint2*>(isv ? g_Vh : g_Kh)
               + (size_t)(blk & 255) * 1024;
    #pragma unroll
    for (int i = 0; i < 4; i++) {
        float4 f = src[tid + i * 256];
        dst[tid + i * 256] =
            make_uint2(h2u(__floats2half2_rn(f.x, f.y)), h2u(__floats2half2_rn(f.z, f.w)));
    }
}

__global__ __launch_bounds__(128)
void sdpa_split_kernel(const float* __restrict__ Q, const int* __restrict__ mask) {
    extern __shared__ char smraw[];
    float* pen_base = reinterpret_cast<float*>(smraw + 2 * STAGE_BYTES);
    const uint32_t smem_u = (uint32_t)__cvta_generic_to_shared(smraw);

    const int tid  = threadIdx.x;
    const int lane = tid & 31;
    const int warp = tid >> 5;
    const int g    = lane >> 2;
    const int tig  = lane & 3;
    const int row8 = lane & 7, matid = lane >> 3;

    const int bx = blockIdx.x;
    const int s  = bx & 3;
    const int b  = (bx >> 2) & 3;
    const int qb = (NQB - 1) - (bx >> 4);             // longest q-blocks first
    const int qm = qb * BM;
    const int p  = bx;
    const int* mb = mask + b * SEQ;
    const int first_b = g_first[b];

    // Fixed-base softmax (no online max); per-row base shift
    // rowadj_r = (r >= first_b) ? 0 : NEGL2 (R11 derivation).
    // Causal term per tile (uniform in t): t<qb none; t==qb per-element;
    // t>qb uniform -NEGL2 (degenerate full-span blocks only).
    const int n_tiles = (first_b <= qm) ? (qb + 1) : (SEQ / BN);

    const int chunk = (n_tiles + NSPLIT - 1) / NSPLIT;
    const int t_beg = s * chunk;
    const int t_end = min(t_beg + chunk, n_tiles);

    const int lr0 = warp * 16 + g;
    const int lr1 = lr0 + 8;

    if (t_beg >= t_end) {                             // empty split: sentinel
        if (tig == 0) {
            g_l[p * BM + lr0] = 0.0f;
            g_l[p * BM + lr1] = 0.0f;
        }
        return;
    }

    const int r0 = qm + lr0;
    const int r1 = qm + lr1;
    const float adj0 = (r0 >= first_b) ? 0.0f : NEGL2;
    const float adj1 = (r1 >= first_b) ? 0.0f : NEGL2;

    // Q fragments (fp16, m16n8k16 A layout), 4 k-chunks x 4 regs
    uint32_t qf[4][4];
    {
        const float* q0 = Q + ((size_t)b * SEQ + r0) * DIM;
        const float* q1 = Q + ((size_t)b * SEQ + r1) * DIM;
        #pragma unroll
        for (int kc = 0; kc < 4; kc++) {
            float2 x0 = *reinterpret_cast<const float2*>(q0 + kc * 16 + 2 * tig);
            float2 x1 = *reinterpret_cast<const float2*>(q1 + kc * 16 + 2 * tig);
            float2 y0 = *reinterpret_cast<const float2*>(q0 + kc * 16 + 8 + 2 * tig);
            float2 y1 = *reinterpret_cast<const float2*>(q1 + kc * 16 + 8 + 2 * tig);
            qf[kc][0] = h2u(__floats2half2_rn(x0.x, x0.y));
            qf[kc][1] = h2u(__floats2half2_rn(x1.x, x1.y));
            qf[kc][2] = h2u(__floats2half2_rn(y0.x, y0.y));
            qf[kc][3] = h2u(__floats2half2_rn(y1.x, y1.y));
        }
    }

    float o[8][4];
    #pragma unroll
    for (int i = 0; i < 8; i++)
        o[i][0] = o[i][1] = o[i][2] = o[i][3] = 0.0f;
    float l0 = 0.0f, l1 = 0.0f;

    const char* kgbase = reinterpret_cast<const char*>(g_Kh + ((size_t)b * SEQ) * DIM);
    const char* vgbase = reinterpret_cast<const char*>(g_Vh + ((size_t)b * SEQ) * DIM);

    auto issue = [&](int t, int st) {
        const int kv0 = t * BN;
        const char* ksrc = kgbase + (size_t)kv0 * DIM * 2;
        const char* vsrc = vgbase + (size_t)kv0 * DIM * 2;
        char* kdst = smraw + st * STAGE_BYTES;
        char* vdst = kdst + 64 * ROWB;
        #pragma unroll
        for (int i = 0; i < 4; i++) {
            const int c = tid + i * 128;              // 0..511
            const int row = c >> 3, seg = c & 7;
            uint32_t ka = (uint32_t)__cvta_generic_to_shared(kdst + row * ROWB + seg * 16);
            asm volatile("cp.async.cg.shared.global [%0], [%1], 16;"
                :: "r"(ka), "l"(ksrc + (row * DIM + seg * 8) * 2));
            uint32_t va = (uint32_t)__cvta_generic_to_shared(vdst + row * ROWB + seg * 16);
            asm volatile("cp.async.cg.shared.global [%0], [%1], 16;"
                :: "r"(va), "l"(vsrc + (row * DIM + seg * 8) * 2));
        }
        float* penf = pen_base + st * BN;
        if (tid < BN) penf[tid] = mb[kv0 + tid] ? 0.0f : -NEGL2;
        asm volatile("cp.async.commit_group;");
    };

    issue(t_beg, 0);

    for (int t = t_beg; t < t_end; t++) {
        const int st  = (t - t_beg) & 1;
        const int kv0 = t * BN;

        if (t + 1 < t_end) {
            issue(t + 1, st ^ 1);
            asm volatile("cp.async.wait_group 1;");
        } else {
            asm volatile("cp.async.wait_group 0;");
        }
        __syncthreads();

        const uint32_t kbase_u = smem_u + st * STAGE_BYTES;
        const uint32_t vbase_u = kbase_u + 64 * ROWB;
        const float* penf = pen_base + st * BN;

        // ---- S = Q K^T : B fragments via ldmatrix.x4 on K tile ----
        float sc[8][4];
        #pragma unroll
        for (int nc = 0; nc < 8; nc++)
            sc[nc][0] = sc[nc][1] = sc[nc][2] = sc[nc][3] = 0.0f;
        #pragma unroll
        for (int kc = 0; kc < 4; kc++) {
            #pragma unroll
            for (int np = 0; np < 4; np++) {
                uint32_t addr = kbase_u + ((2 * np + (matid >> 1)) * 8 + row8) * ROWB
                              + (kc * 16 + (matid & 1) * 8) * 2;
                uint32_t r0_, r1_, r2_, r3_;
                ldsm_x4(r0_, r1_, r2_, r3_, addr);
                mma_f16(sc[2 * np],     qf[kc], r0_, r1_);
                mma_f16(sc[2 * np + 1], qf[kc], r2_, r3_);
            }
        }

        // ---- P = exp2(...) ; causal term specialized on uniform t ----
        if (t == qb) {                                 // diagonal tile
            #pragma unroll
            for (int nc = 0; nc < 8; nc++) {
                const int c0 = kv0 + nc * 8 + 2 * tig;
                float2 pn = *reinterpret_cast<const float2*>(penf + nc * 8 + 2 * tig);
                sc[nc][0] = ex2(sc[nc][0] * SCL2 + pn.x + adj0 + (c0     > r0 ? -NEGL2 : 0.0f));
                sc[nc][1] = ex2(sc[nc][1] * SCL2 + pn.y + adj0 + (c0 + 1 > r0 ? -NEGL2 : 0.0f));
                sc[nc][2] = ex2(sc[nc][2] * SCL2 + pn.x + adj1 + (c0     > r1 ? -NEGL2 : 0.0f));
                sc[nc][3] = ex2(sc[nc][3] * SCL2 + pn.y + adj1 + (c0 + 1 > r1 ? -NEGL2 : 0.0f));
                l0 += sc[nc][0] + sc[nc][1];
                l1 += sc[nc][2] + sc[nc][3];
            }
        } else {
            const float cc = (t > qb) ? -NEGL2 : 0.0f; // uniform causal term
            const float a0 = adj0 + cc, a1 = adj1 + cc;
            #pragma unroll
            for (int nc = 0; nc < 8; nc++) {
                float2 pn = *reinterpret_cast<const float2*>(penf + nc * 8 + 2 * tig);
                sc[nc][0] = ex2(sc[nc][0] * SCL2 + pn.x + a0);
                sc[nc][1] = ex2(sc[nc][1] * SCL2 + pn.y + a0);
                sc[nc][2] = ex2(sc[nc][2] * SCL2 + pn.x + a1);
                sc[nc][3] = ex2(sc[nc][3] * SCL2 + pn.y + a1);
                l0 += sc[nc][0] + sc[nc][1];
                l1 += sc[nc][2] + sc[nc][3];
            }
        }

        // ---- O += P V : A = packed S frags; B via ldmatrix.x4.TRANS on the
        //      row-major [k][d] V tile (block (k,d) transposed == [d][k] frag;
        //      matid bit0 -> k-half rows, bit1 -> d-half cols, pairing as before) ----
        #pragma unroll
        for (int kk = 0; kk < 4; kk++) {
            uint32_t pf[4];
            pf[0] = h2u(__floats2half2_rn(sc[2 * kk][0],     sc[2 * kk][1]));
            pf[1] = h2u(__floats2half2_rn(sc[2 * kk][2],     sc[2 * kk][3]));
            pf[2] = h2u(__floats2half2_rn(sc[2 * kk + 1][0], sc[2 * kk + 1][1]));
            pf[3] = h2u(__floats2half2_rn(sc[2 * kk + 1][2], sc[2 * kk + 1][3]));
            #pragma unroll
            for (int op = 0; op < 4; op++) {
                uint32_t addr = vbase_u + (kk * 16 + (matid & 1) * 8 + row8) * ROWB
                              + ((2 * op + (matid >> 1)) * 8) * 2;
                uint32_t r0_, r1_, r2_, r3_;
                ldsm_x4t(r0_, r1_, r2_, r3_, addr);
                mma_f16(o[2 * op],     pf, r0_, r1_);
                mma_f16(o[2 * op + 1], pf, r2_, r3_);
            }
        }
        __syncthreads();
    }

    // quad-reduce l (full row sum)
    l0 += __shfl_xor_sync(0xffffffffu, l0, 1);
    l0 += __shfl_xor_sync(0xffffffffu, l0, 2);
    l1 += __shfl_xor_sync(0xffffffffu, l1, 1);
    l1 += __shfl_xor_sync(0xffffffffu, l1, 2);

    float* po0 = g_o + ((size_t)p * BM + lr0) * DIM;
    float* po1 = g_o + ((size_t)p * BM + lr1) * DIM;
    #pragma unroll
    for (int oc = 0; oc < 8; oc++) {
        const int c = oc * 8 + 2 * tig;
        *reinterpret_cast<float2*>(po0 + c) = make_float2(o[oc][0], o[oc][1]);
        *reinterpret_cast<float2*>(po1 + c) = make_float2(o[oc][2], o[oc][3]);
    }
    if (tig == 0) {
        g_l[p * BM + lr0] = l0;
        g_l[p * BM + lr1] = l1;
    }
}

__global__ __launch_bounds__(256)
void combine_kernel(float* __restrict__ O) {
    const int t  = blockIdx.x * 256 + threadIdx.x;
    const int fq  = t & 15;
    const int row = (t >> 4) & 63;
    const int qb  = (t >> 10) & 63;
    const int b   = t >> 16;

    const int qidx  = (NQB - 1) - qb;
    const int pbase = (qidx << 4) | (b << 2);

    // all splits share the same fixed exp2 base per row -> plain sums
    float L = 0.0f;
    float4 acc = make_float4(0.f, 0.f, 0.f, 0.f);
    #pragma unroll
    for (int s2 = 0; s2 < NSPLIT; s2++) {
        float lv = g_l[(pbase + s2) * BM + row];
        L += lv;
        if (lv > 0.0f) {
            float4 v = reinterpret_cast<const float4*>(
                g_o + ((size_t)(pbase + s2) * BM + row) * DIM)[fq];
            acc.x += v.x; acc.y += v.y; acc.z += v.z; acc.w += v.w;
        }
    }
    const float inv = 1.0f / L;
    reinterpret_cast<float4*>(O + ((size_t)b * SEQ + qb * BM + row) * DIM)[fq] =
        make_float4(acc.x * inv, acc.y * inv, acc.z * inv, acc.w * inv);
}

extern "C" void kernel_launch(void* const* d_in, const int* in_sizes, int n_in,
                              void* d_out, int out_size) {
    const float* Q    = (const float*)d_in[0];
    const float* K    = (const float*)d_in[1];
    const float* V    = (const float*)d_in[2];
    const int*   mask = (const int*)d_in[3];
    float*       O    = (float*)d_out;

    static bool attr_set = false;
    if (!attr_set) {
        cudaFuncSetAttribute(sdpa_split_kernel,
                             cudaFuncAttributeMaxDynamicSharedMemorySize, SMEM_BYTES);
        attr_set = true;
    }

    conv_kernel<<<NCONV + BATCH, 256>>>(K, V, mask);
    sdpa_split_kernel<<<NP, 128, SMEM_BYTES>>>(Q, mask);
    combine_kernel<<<(BATCH * SEQ * DIM / 4) / 256, 256>>>(O);
}